// round 11
// baseline (speedup 1.0000x reference)
#include <cuda_runtime.h>
#include <math.h>
#include <stdint.h>

// Problem constants
#define BATCH 2
#define SEQ 2048
#define EMB 2048
#define NHEAD 16
#define HDIM 128
#define THREE_E 6144
#define MROWS (BATCH * SEQ)   // 4096
#define GK 2048               // K dim of both GEMMs

// Scratch (device globals — no cudaMalloc allowed)
__device__ float g_qkv[(size_t)MROWS * THREE_E];   // [B*S, 3E] (Q region used)
__device__ float g_attn[(size_t)MROWS * EMB];      // [B*S, E] (tf32-rounded)
__device__ float g_xr[(size_t)MROWS * EMB];        // tf32-rounded x
__device__ float g_wqkvr[(size_t)THREE_E * EMB];   // tf32-rounded W_qkv
__device__ float g_woutr[(size_t)EMB * EMB];       // tf32-rounded W_out
__device__ float g_khi[(size_t)MROWS * EMB];       // K hi split (from GEMM1 epilogue)
__device__ float g_klo[(size_t)MROWS * EMB];       // K lo split
__device__ float g_vr [(size_t)MROWS * EMB];       // V tf32-rounded

// ===========================================================================
// Helpers
// ===========================================================================
__device__ __forceinline__ uint32_t smem_u32(const void* p) {
    uint32_t a;
    asm("{ .reg .u64 t; cvta.to.shared.u64 t, %1; cvt.u32.u64 %0, t; }"
        : "=r"(a) : "l"(p));
    return a;
}

__device__ __forceinline__ float rna_tf32(float x) {
    uint32_t u;
    asm("cvt.rna.tf32.f32 %0, %1;" : "=r"(u) : "f"(x));
    return __uint_as_float(u);
}

// Fast exp2 via MUFU (ex2.approx): max rel err ~2^-22, -inf -> 0.
__device__ __forceinline__ float ex2(float x) {
    float y;
    asm("ex2.approx.f32 %0, %1;" : "=f"(y) : "f"(x));
    return y;
}

#define CP_ASYNC16(dst, src) \
    asm volatile("cp.async.cg.shared.global [%0], [%1], 16;" :: "r"(dst), "l"(src))
#define CP_COMMIT() asm volatile("cp.async.commit_group;" ::: "memory")
#define CP_WAIT(n)  asm volatile("cp.async.wait_group %0;" :: "n"(n) : "memory")

// mma.sync m16n8k8 tf32: D = A*B + C   (A 16x8 row, B 8x8 col)
__device__ __forceinline__ void mma_tf32(float& d0, float& d1, float& d2, float& d3,
                                         uint32_t a0, uint32_t a1, uint32_t a2, uint32_t a3,
                                         uint32_t b0, uint32_t b1,
                                         float c0, float c1, float c2, float c3) {
    asm volatile(
        "mma.sync.aligned.m16n8k8.row.col.f32.tf32.tf32.f32 "
        "{%0,%1,%2,%3}, {%4,%5,%6,%7}, {%8,%9}, {%10,%11,%12,%13};"
        : "=f"(d0), "=f"(d1), "=f"(d2), "=f"(d3)
        : "r"(a0), "r"(a1), "r"(a2), "r"(a3), "r"(b0), "r"(b1),
          "f"(c0), "f"(c1), "f"(c2), "f"(c3));
}

__device__ __forceinline__ void ldsm_x4(uint32_t& r0, uint32_t& r1,
                                        uint32_t& r2, uint32_t& r3, uint32_t addr) {
    asm volatile("ldmatrix.sync.aligned.m8n8.x4.shared.b16 {%0,%1,%2,%3}, [%4];"
                 : "=r"(r0), "=r"(r1), "=r"(r2), "=r"(r3) : "r"(addr));
}
__device__ __forceinline__ void ldsm_x2(uint32_t& r0, uint32_t& r1, uint32_t addr) {
    asm volatile("ldmatrix.sync.aligned.m8n8.x2.shared.b16 {%0,%1}, [%2];"
                 : "=r"(r0), "=r"(r1) : "r"(addr));
}

// ===========================================================================
// tf32 rounding kernel (elementwise, float4)
// ===========================================================================
__global__ __launch_bounds__(256)
void round_tf32_kernel(const float* __restrict__ in, float* __restrict__ out, int n4)
{
    int i = blockIdx.x * 256 + threadIdx.x;
    if (i >= n4) return;
    float4 v = ((const float4*)in)[i];
    v.x = rna_tf32(v.x); v.y = rna_tf32(v.y);
    v.z = rna_tf32(v.z); v.w = rna_tf32(v.w);
    ((float4*)out)[i] = v;
}

// ===========================================================================
// tf32 mma.sync GEMM: C[M,N] = A[M,K] * Bw[N,K]^T + bias[N]
// R9 champion mainloop. R11: optional "qkv split" epilogue — for K-region
// columns write tf32 hi/lo to khi/klo, for V-region write rna to vr
// (bit-identical to the former in-kernel attention split).
// ===========================================================================
#define BKC 32
#define SROW 36
#define STAGE_FLOATS (128 * SROW)
#define STAGE_BYTES  (2 * STAGE_FLOATS * 4)
#define NSTG 3
#define GEMM_SMEM (NSTG * STAGE_BYTES)      // 110592

__global__ __launch_bounds__(256, 2)
void gemm_tf32_mma(const float* __restrict__ A, const float* __restrict__ Bw,
                   const float* __restrict__ bias, float* __restrict__ C, int N,
                   int split_mode,
                   float* __restrict__ khi, float* __restrict__ klo,
                   float* __restrict__ vr)
{
    extern __shared__ float sm[];

    const int tid  = threadIdx.x;
    const int wid  = tid >> 5;
    const int lane = tid & 31;
    const int wm   = wid & 1;
    const int wn   = wid >> 1;
    const int lr   = lane >> 2;
    const int lc   = lane & 3;
    const long m0 = (long)blockIdx.y * 128;
    const long n0 = (long)blockIdx.x * 128;

    const float* Abase = A  + m0 * GK;
    const float* Bbase = Bw + n0 * GK;

    const uint32_t smem0 = smem_u32(sm);
    const uint32_t aoff = ((wm * 64 + (lane & 15)) * SROW + 4 * (lane >> 4)) * 4;
    const uint32_t boff = ((wn * 32 + (lane & 7)) * SROW + 4 * ((lane >> 3) & 1)) * 4
                          + STAGE_FLOATS * 4;

    const int ld_row0 = tid >> 3;
    const int ld_c    = tid & 7;

    float acc[4][4][4];
#pragma unroll
    for (int i = 0; i < 4; ++i)
#pragma unroll
        for (int j = 0; j < 4; ++j)
#pragma unroll
            for (int q = 0; q < 4; ++q) acc[i][j][q] = 0.0f;

#pragma unroll
    for (int p = 0; p < 2; ++p) {
        uint32_t sa = smem0 + p * STAGE_BYTES;
        uint32_t sb = sa + STAGE_FLOATS * 4;
        const float* Ab = Abase + p * BKC;
        const float* Bb = Bbase + p * BKC;
#pragma unroll
        for (int it = 0; it < 4; ++it) {
            int row = ld_row0 + it * 32;
            CP_ASYNC16(sa + row * (SROW * 4) + ld_c * 16, Ab + (long)row * GK + ld_c * 4);
            CP_ASYNC16(sb + row * (SROW * 4) + ld_c * 16, Bb + (long)row * GK + ld_c * 4);
        }
        CP_COMMIT();
    }

    const int KT = GK / BKC;   // 64
    for (int kt = 0; kt < KT; ++kt) {
        CP_WAIT(1);
        __syncthreads();

        const uint32_t stage = smem0 + (kt % NSTG) * STAGE_BYTES;

        const int nf = kt + 2;
        const bool do_load = (nf < KT);
        const uint32_t nsa = smem0 + (nf % NSTG) * STAGE_BYTES;
        const uint32_t nsb = nsa + STAGE_FLOATS * 4;
        const float* An = Abase + (long)nf * BKC;
        const float* Bn = Bbase + (long)nf * BKC;

#pragma unroll
        for (int k = 0; k < 4; ++k) {
            const uint32_t kb = k * 32;
            uint32_t af[4][4], bf[4][2];
#pragma unroll
            for (int mt = 0; mt < 4; ++mt)
                ldsm_x4(af[mt][0], af[mt][1], af[mt][2], af[mt][3],
                        stage + aoff + mt * (16 * SROW * 4) + kb);
#pragma unroll
            for (int nt = 0; nt < 4; ++nt)
                ldsm_x2(bf[nt][0], bf[nt][1],
                        stage + boff + nt * (8 * SROW * 4) + kb);

            if (do_load) {
                int row = ld_row0 + k * 32;
                CP_ASYNC16(nsa + row * (SROW * 4) + ld_c * 16, An + (long)row * GK + ld_c * 4);
                CP_ASYNC16(nsb + row * (SROW * 4) + ld_c * 16, Bn + (long)row * GK + ld_c * 4);
            }

#pragma unroll
            for (int mt = 0; mt < 4; ++mt)
#pragma unroll
                for (int nt = 0; nt < 4; ++nt)
                    mma_tf32(acc[mt][nt][0], acc[mt][nt][1], acc[mt][nt][2], acc[mt][nt][3],
                             af[mt][0], af[mt][1], af[mt][2], af[mt][3],
                             bf[nt][0], bf[nt][1],
                             acc[mt][nt][0], acc[mt][nt][1], acc[mt][nt][2], acc[mt][nt][3]);
        }
        CP_COMMIT();
    }

    // Epilogue: bias + either plain store or qkv-split store.
#pragma unroll
    for (int mt = 0; mt < 4; ++mt) {
        const long r0 = m0 + wm * 64 + mt * 16 + lr;
        const long r1 = r0 + 8;
#pragma unroll
        for (int nt = 0; nt < 4; ++nt) {
            const long cc = n0 + wn * 32 + nt * 8 + 2 * lc;
            const float b0 = bias[cc], b1 = bias[cc + 1];
            float v00 = acc[mt][nt][0] + b0, v01 = acc[mt][nt][1] + b1;   // row r0
            float v10 = acc[mt][nt][2] + b0, v11 = acc[mt][nt][3] + b1;   // row r1

            if (split_mode && cc >= EMB) {
                const long cc2 = cc - EMB;
                if (cc2 < EMB) {
                    // K region: hi/lo tf32 split (bit-identical to in-kernel split)
                    float h00 = rna_tf32(v00), l00 = rna_tf32(v00 - h00);
                    float h01 = rna_tf32(v01), l01 = rna_tf32(v01 - h01);
                    float h10 = rna_tf32(v10), l10 = rna_tf32(v10 - h10);
                    float h11 = rna_tf32(v11), l11 = rna_tf32(v11 - h11);
                    *(float2*)(khi + r0 * EMB + cc2) = make_float2(h00, h01);
                    *(float2*)(klo + r0 * EMB + cc2) = make_float2(l00, l01);
                    *(float2*)(khi + r1 * EMB + cc2) = make_float2(h10, h11);
                    *(float2*)(klo + r1 * EMB + cc2) = make_float2(l10, l11);
                } else {
                    // V region: rna rounding
                    const long cc3 = cc2 - EMB;
                    *(float2*)(vr + r0 * EMB + cc3) =
                        make_float2(rna_tf32(v00), rna_tf32(v01));
                    *(float2*)(vr + r1 * EMB + cc3) =
                        make_float2(rna_tf32(v10), rna_tf32(v11));
                }
            } else {
                *(float2*)(C + r0 * N + cc) = make_float2(v00, v01);
                *(float2*)(C + r1 * N + cc) = make_float2(v10, v11);
            }
        }
    }
}

// ===========================================================================
// Tensor-core flash attention (causal), tf32 mma.sync.
// R11: K/V pre-split by GEMM1 epilogue -> kt store phase is pure STS
// (no cvt chain). Register prefetch pipeline and numerics identical to R10.
// ===========================================================================
#define ATT_QHI 0
#define ATT_QLO 16896
#define ATT_KHI 33792
#define ATT_KLO 38016
#define ATT_VS  42240
#define ATT_PS  46592
#define ATT_SMEM_FLOATS 51200
#define ATT_SMEM_BYTES (ATT_SMEM_FLOATS * 4)   // 204800

__global__ __launch_bounds__(256, 1)
void flash_attn_tc(const float* __restrict__ qkv,
                   const float* __restrict__ khi, const float* __restrict__ klo,
                   const float* __restrict__ vrg, float* __restrict__ out)
{
    extern __shared__ float sm[];
    float* Qhi = sm + ATT_QHI;
    float* Qlo = sm + ATT_QLO;
    float* Khi = sm + ATT_KHI;
    float* Klo = sm + ATT_KLO;
    float* Vsm = sm + ATT_VS;
    float* Psm = sm + ATT_PS;

    const int tid  = threadIdx.x;
    const int wid  = tid >> 5;
    const int lane = tid & 31;
    const int lr   = lane >> 2;
    const int lc   = lane & 3;
    const int qi   = (int)(gridDim.x - 1) - (int)blockIdx.x;
    const int h    = blockIdx.y;
    const int b    = blockIdx.z;
    const int q0   = qi * 128;
    const int m0   = wid * 16;

    const float SCL2E = 0.08838834764831845f * 1.4426950408889634f;

    const float* baseQ = qkv + ((long)b * SEQ) * THREE_E + h * HDIM;
    const long kvbase = ((long)b * SEQ) * EMB + h * HDIM;

    // This thread's 4 slots within a 32x128 tile: row = slot>>5, d = (slot&31)*4
    const int srow[4] = { tid >> 5, (tid + 256) >> 5, (tid + 512) >> 5, (tid + 768) >> 5 };
    const int sd     = (tid & 31) * 4;

    // ---- Prefetch tile 0 (pre-split) into registers ----
    float4 khr[4], klr[4], vvr[4];
#pragma unroll
    for (int i = 0; i < 4; ++i) {
        const long gr = kvbase + (long)srow[i] * EMB + sd;
        khr[i] = *(const float4*)(khi + gr);
        klr[i] = *(const float4*)(klo + gr);
        vvr[i] = *(const float4*)(vrg + gr);
    }

    // ---- Load Q tile with hi/lo tf32 split (overlaps with prefetch) ----
#pragma unroll
    for (int i = 0; i < 16; ++i) {
        int slot = tid + i * 256;
        int row  = slot >> 5;
        int d    = (slot & 31) * 4;
        float4 v = *(const float4*)(baseQ + (long)(q0 + row) * THREE_E + d);
        float4 hi, lo;
        hi.x = rna_tf32(v.x); lo.x = rna_tf32(v.x - hi.x);
        hi.y = rna_tf32(v.y); lo.y = rna_tf32(v.y - hi.y);
        hi.z = rna_tf32(v.z); lo.z = rna_tf32(v.z - hi.z);
        hi.w = rna_tf32(v.w); lo.w = rna_tf32(v.w - hi.w);
        *(float4*)(Qhi + row * 132 + d) = hi;
        *(float4*)(Qlo + row * 132 + d) = lo;
    }

    float oacc[16][4];
#pragma unroll
    for (int nt = 0; nt < 16; ++nt)
#pragma unroll
        for (int q = 0; q < 4; ++q) oacc[nt][q] = 0.0f;
    float m_lo = -1e30f, m_hi = -1e30f;
    float l_lo = 0.0f,   l_hi = 0.0f;

    const int row_lo = q0 + m0 + lr;
    const int row_hi = row_lo + 8;

    const int ktEnd = 4 * qi + 3;
    for (int kt = 0; kt <= ktEnd; ++kt) {
        __syncthreads();   // previous iteration done reading K/V/P smem

        // ---- Store prefetched tile kt to smem (pure STS, no cvt) ----
#pragma unroll
        for (int i = 0; i < 4; ++i) {
            const int row = srow[i];
            *(float4*)(Khi + row * 132 + sd) = khr[i];
            *(float4*)(Klo + row * 132 + sd) = klr[i];
            *(float4*)(Vsm + row * 136 + sd) = vvr[i];
        }
        __syncthreads();

        // ---- Prefetch tile kt+1 into registers (overlaps with compute) ----
        if (kt < ktEnd) {
            const long tb = kvbase + (long)((kt + 1) * 32) * EMB + sd;
#pragma unroll
            for (int i = 0; i < 4; ++i) {
                const long gr = tb + (long)srow[i] * EMB;
                khr[i] = *(const float4*)(khi + gr);
                klr[i] = *(const float4*)(klo + gr);
                vvr[i] = *(const float4*)(vrg + gr);
            }
        }

        if (kt * 32 > q0 + m0 + 15) continue;   // warp-tile fully masked

        float sacc[4][4];
#pragma unroll
        for (int nt = 0; nt < 4; ++nt)
#pragma unroll
            for (int q = 0; q < 4; ++q) sacc[nt][q] = 0.0f;

        const uint32_t* qh = (const uint32_t*)Qhi;
        const uint32_t* ql = (const uint32_t*)Qlo;
        const uint32_t* kh = (const uint32_t*)Khi;
        const uint32_t* kl = (const uint32_t*)Klo;

#pragma unroll
        for (int kd = 0; kd < 16; ++kd) {
            const int k0 = kd * 8;
            const int ra = (m0 + lr) * 132 + k0 + lc;
            const int rb = ra + 8 * 132;
            uint32_t ah0 = qh[ra], ah1 = qh[rb], ah2 = qh[ra + 4], ah3 = qh[rb + 4];
            uint32_t al0 = ql[ra], al1 = ql[rb], al2 = ql[ra + 4], al3 = ql[rb + 4];
#pragma unroll
            for (int nt = 0; nt < 4; ++nt) {
                const int rk = (nt * 8 + lr) * 132 + k0 + lc;
                uint32_t bh0 = kh[rk], bh1 = kh[rk + 4];
                uint32_t bl0 = kl[rk], bl1 = kl[rk + 4];
                mma_tf32(sacc[nt][0], sacc[nt][1], sacc[nt][2], sacc[nt][3],
                         ah0, ah1, ah2, ah3, bh0, bh1,
                         sacc[nt][0], sacc[nt][1], sacc[nt][2], sacc[nt][3]);
                mma_tf32(sacc[nt][0], sacc[nt][1], sacc[nt][2], sacc[nt][3],
                         ah0, ah1, ah2, ah3, bl0, bl1,
                         sacc[nt][0], sacc[nt][1], sacc[nt][2], sacc[nt][3]);
                mma_tf32(sacc[nt][0], sacc[nt][1], sacc[nt][2], sacc[nt][3],
                         al0, al1, al2, al3, bh0, bh1,
                         sacc[nt][0], sacc[nt][1], sacc[nt][2], sacc[nt][3]);
            }
        }

        const bool tail = (kt >= 4 * qi);
        float rm_lo = -INFINITY, rm_hi = -INFINITY;
#pragma unroll
        for (int nt = 0; nt < 4; ++nt) {
            const int c0 = kt * 32 + nt * 8 + 2 * lc;
            float v0 = sacc[nt][0] * SCL2E;
            float v1 = sacc[nt][1] * SCL2E;
            float v2 = sacc[nt][2] * SCL2E;
            float v3 = sacc[nt][3] * SCL2E;
            if (tail) {
                if (c0     > row_lo) v0 = -INFINITY;
                if (c0 + 1 > row_lo) v1 = -INFINITY;
                if (c0     > row_hi) v2 = -INFINITY;
                if (c0 + 1 > row_hi) v3 = -INFINITY;
            }
            sacc[nt][0] = v0; sacc[nt][1] = v1;
            sacc[nt][2] = v2; sacc[nt][3] = v3;
            rm_lo = fmaxf(rm_lo, fmaxf(v0, v1));
            rm_hi = fmaxf(rm_hi, fmaxf(v2, v3));
        }
        rm_lo = fmaxf(rm_lo, __shfl_xor_sync(0xffffffffu, rm_lo, 1));
        rm_lo = fmaxf(rm_lo, __shfl_xor_sync(0xffffffffu, rm_lo, 2));
        rm_hi = fmaxf(rm_hi, __shfl_xor_sync(0xffffffffu, rm_hi, 1));
        rm_hi = fmaxf(rm_hi, __shfl_xor_sync(0xffffffffu, rm_hi, 2));

        const float mn_lo = fmaxf(m_lo, rm_lo);
        const float mn_hi = fmaxf(m_hi, rm_hi);
        const float corr_lo = ex2(m_lo - mn_lo);
        const float corr_hi = ex2(m_hi - mn_hi);
        m_lo = mn_lo; m_hi = mn_hi;

        float ps_lo = 0.0f, ps_hi = 0.0f;
#pragma unroll
        for (int nt = 0; nt < 4; ++nt) {
            float p0 = ex2(sacc[nt][0] - mn_lo);
            float p1 = ex2(sacc[nt][1] - mn_lo);
            float p2 = ex2(sacc[nt][2] - mn_hi);
            float p3 = ex2(sacc[nt][3] - mn_hi);
            ps_lo += p0 + p1;
            ps_hi += p2 + p3;
            float2 w0 = make_float2(rna_tf32(p0), rna_tf32(p1));
            float2 w1 = make_float2(rna_tf32(p2), rna_tf32(p3));
            *(float2*)(Psm + (m0 + lr    ) * 36 + nt * 8 + 2 * lc) = w0;
            *(float2*)(Psm + (m0 + lr + 8) * 36 + nt * 8 + 2 * lc) = w1;
        }
        ps_lo += __shfl_xor_sync(0xffffffffu, ps_lo, 1);
        ps_lo += __shfl_xor_sync(0xffffffffu, ps_lo, 2);
        ps_hi += __shfl_xor_sync(0xffffffffu, ps_hi, 1);
        ps_hi += __shfl_xor_sync(0xffffffffu, ps_hi, 2);
        l_lo = l_lo * corr_lo + ps_lo;
        l_hi = l_hi * corr_hi + ps_hi;

#pragma unroll
        for (int nt = 0; nt < 16; ++nt) {
            oacc[nt][0] *= corr_lo; oacc[nt][1] *= corr_lo;
            oacc[nt][2] *= corr_hi; oacc[nt][3] *= corr_hi;
        }
        __syncwarp();

        const uint32_t* ps = (const uint32_t*)Psm;
        const uint32_t* vs = (const uint32_t*)Vsm;
#pragma unroll
        for (int kd = 0; kd < 4; ++kd) {
            const int k0 = kd * 8;
            const int ra = (m0 + lr) * 36 + k0 + lc;
            const int rb = ra + 8 * 36;
            uint32_t a0 = ps[ra], a1 = ps[rb], a2 = ps[ra + 4], a3 = ps[rb + 4];
#pragma unroll
            for (int nt = 0; nt < 16; ++nt) {
                uint32_t b0 = vs[(k0 + lc    ) * 136 + nt * 8 + lr];
                uint32_t b1 = vs[(k0 + lc + 4) * 136 + nt * 8 + lr];
                mma_tf32(oacc[nt][0], oacc[nt][1], oacc[nt][2], oacc[nt][3],
                         a0, a1, a2, a3, b0, b1,
                         oacc[nt][0], oacc[nt][1], oacc[nt][2], oacc[nt][3]);
            }
        }
    }

    const float inv_lo = 1.0f / l_lo;
    const float inv_hi = 1.0f / l_hi;
    const long grow_lo = (long)b * SEQ + row_lo;
    const long grow_hi = (long)b * SEQ + row_hi;
#pragma unroll
    for (int nt = 0; nt < 16; ++nt) {
        const int col = h * HDIM + nt * 8 + 2 * lc;
        float2 w0 = make_float2(rna_tf32(oacc[nt][0] * inv_lo),
                                rna_tf32(oacc[nt][1] * inv_lo));
        float2 w1 = make_float2(rna_tf32(oacc[nt][2] * inv_hi),
                                rna_tf32(oacc[nt][3] * inv_hi));
        *(float2*)(out + grow_lo * EMB + col) = w0;
        *(float2*)(out + grow_hi * EMB + col) = w1;
    }
}

// ===========================================================================
// Host launcher
// ===========================================================================
extern "C" void kernel_launch(void* const* d_in, const int* in_sizes, int n_in,
                              void* d_out, int out_size)
{
    const float* x     = (const float*)d_in[0];
    const float* Wqkv  = (const float*)d_in[1];
    const float* bqkv  = (const float*)d_in[2];
    const float* Wout  = (const float*)d_in[3];
    const float* bout  = (const float*)d_in[4];
    float* out = (float*)d_out;

    float *qkvp, *attnp, *xr, *wqkvr, *woutr, *khip, *klop, *vrp;
    cudaGetSymbolAddress((void**)&qkvp,  g_qkv);
    cudaGetSymbolAddress((void**)&attnp, g_attn);
    cudaGetSymbolAddress((void**)&xr,    g_xr);
    cudaGetSymbolAddress((void**)&wqkvr, g_wqkvr);
    cudaGetSymbolAddress((void**)&woutr, g_woutr);
    cudaGetSymbolAddress((void**)&khip,  g_khi);
    cudaGetSymbolAddress((void**)&klop,  g_klo);
    cudaGetSymbolAddress((void**)&vrp,   g_vr);

    // 0) tf32 pre-rounding of GEMM operands
    {
        int n4x = MROWS * EMB / 4;
        int n4q = THREE_E * EMB / 4;
        int n4o = EMB * EMB / 4;
        round_tf32_kernel<<<(n4x + 255) / 256, 256>>>(x, xr, n4x);
        round_tf32_kernel<<<(n4q + 255) / 256, 256>>>(Wqkv, wqkvr, n4q);
        round_tf32_kernel<<<(n4o + 255) / 256, 256>>>(Wout, woutr, n4o);
    }

    cudaFuncSetAttribute(gemm_tf32_mma, cudaFuncAttributeMaxDynamicSharedMemorySize, GEMM_SMEM);

    // 1) QKV projection with fused K hi/lo split + V rounding in epilogue
    {
        dim3 grid(THREE_E / 128, MROWS / 128);   // 48 x 32
        gemm_tf32_mma<<<grid, 256, GEMM_SMEM>>>(xr, wqkvr, bqkv, qkvp, THREE_E,
                                                1, khip, klop, vrp);
    }

    // 2) Tensor-core flash attention (pre-split K/V, pure-STS store phase)
    {
        cudaFuncSetAttribute(flash_attn_tc, cudaFuncAttributeMaxDynamicSharedMemorySize, ATT_SMEM_BYTES);
        dim3 grid(SEQ / 128, NHEAD, BATCH);
        flash_attn_tc<<<grid, 256, ATT_SMEM_BYTES>>>(qkvp, khip, klop, vrp, attnp);
    }

    // 3) Output projection (plain epilogue)
    {
        dim3 grid(EMB / 128, MROWS / 128);       // 16 x 32
        gemm_tf32_mma<<<grid, 256, GEMM_SMEM>>>(attnp, woutr, bout, out, EMB,
                                                0, nullptr, nullptr, nullptr);
    }
}

// round 12
// speedup vs baseline: 1.0580x; 1.0580x over previous
#include <cuda_runtime.h>
#include <math.h>
#include <stdint.h>

// Problem constants
#define BATCH 2
#define SEQ 2048
#define EMB 2048
#define NHEAD 16
#define HDIM 128
#define THREE_E 6144
#define MROWS (BATCH * SEQ)   // 4096
#define GK 2048               // K dim of both GEMMs

// Scratch (device globals — no cudaMalloc allowed)
__device__ float g_qkv[(size_t)MROWS * THREE_E];   // [B*S, 3E]
__device__ float g_attn[(size_t)MROWS * EMB];      // [B*S, E] (tf32-rounded)
__device__ float g_xr[(size_t)MROWS * EMB];        // tf32-rounded x
__device__ float g_wqkvr[(size_t)THREE_E * EMB];   // tf32-rounded W_qkv
__device__ float g_woutr[(size_t)EMB * EMB];       // tf32-rounded W_out

// ===========================================================================
// Helpers
// ===========================================================================
__device__ __forceinline__ uint32_t smem_u32(const void* p) {
    uint32_t a;
    asm("{ .reg .u64 t; cvta.to.shared.u64 t, %1; cvt.u32.u64 %0, t; }"
        : "=r"(a) : "l"(p));
    return a;
}

__device__ __forceinline__ float rna_tf32(float x) {
    uint32_t u;
    asm("cvt.rna.tf32.f32 %0, %1;" : "=r"(u) : "f"(x));
    return __uint_as_float(u);
}

// Fast exp2 via MUFU (ex2.approx): max rel err ~2^-22, -inf -> 0.
__device__ __forceinline__ float ex2(float x) {
    float y;
    asm("ex2.approx.f32 %0, %1;" : "=f"(y) : "f"(x));
    return y;
}

#define CP_ASYNC16(dst, src) \
    asm volatile("cp.async.cg.shared.global [%0], [%1], 16;" :: "r"(dst), "l"(src))
#define CP_COMMIT() asm volatile("cp.async.commit_group;" ::: "memory")
#define CP_WAIT(n)  asm volatile("cp.async.wait_group %0;" :: "n"(n) : "memory")

// mma.sync m16n8k8 tf32: D = A*B + C   (A 16x8 row, B 8x8 col)
__device__ __forceinline__ void mma_tf32(float& d0, float& d1, float& d2, float& d3,
                                         uint32_t a0, uint32_t a1, uint32_t a2, uint32_t a3,
                                         uint32_t b0, uint32_t b1,
                                         float c0, float c1, float c2, float c3) {
    asm volatile(
        "mma.sync.aligned.m16n8k8.row.col.f32.tf32.tf32.f32 "
        "{%0,%1,%2,%3}, {%4,%5,%6,%7}, {%8,%9}, {%10,%11,%12,%13};"
        : "=f"(d0), "=f"(d1), "=f"(d2), "=f"(d3)
        : "r"(a0), "r"(a1), "r"(a2), "r"(a3), "r"(b0), "r"(b1),
          "f"(c0), "f"(c1), "f"(c2), "f"(c3));
}

__device__ __forceinline__ void ldsm_x4(uint32_t& r0, uint32_t& r1,
                                        uint32_t& r2, uint32_t& r3, uint32_t addr) {
    asm volatile("ldmatrix.sync.aligned.m8n8.x4.shared.b16 {%0,%1,%2,%3}, [%4];"
                 : "=r"(r0), "=r"(r1), "=r"(r2), "=r"(r3) : "r"(addr));
}
__device__ __forceinline__ void ldsm_x2(uint32_t& r0, uint32_t& r1, uint32_t addr) {
    asm volatile("ldmatrix.sync.aligned.m8n8.x2.shared.b16 {%0,%1}, [%2];"
                 : "=r"(r0), "=r"(r1) : "r"(addr));
}

// ===========================================================================
// Fused tf32 rounding kernel (x, W_qkv, W_out in one launch)
// ===========================================================================
#define N4X (MROWS * EMB / 4)        // 2,097,152
#define N4Q (THREE_E * EMB / 4)      // 3,145,728
#define N4O (EMB * EMB / 4)          // 1,048,576

__global__ __launch_bounds__(256)
void round_all_kernel(const float* __restrict__ x,  float* __restrict__ xr,
                      const float* __restrict__ wq, float* __restrict__ wqr,
                      const float* __restrict__ wo, float* __restrict__ wor)
{
    int i = blockIdx.x * 256 + threadIdx.x;
    const float4* src;
    float4* dst;
    int j;
    if (i < N4X)              { src = (const float4*)x;  dst = (float4*)xr;  j = i; }
    else if (i < N4X + N4Q)   { src = (const float4*)wq; dst = (float4*)wqr; j = i - N4X; }
    else if (i < N4X+N4Q+N4O) { src = (const float4*)wo; dst = (float4*)wor; j = i - N4X - N4Q; }
    else return;
    float4 v = src[j];
    v.x = rna_tf32(v.x); v.y = rna_tf32(v.y);
    v.z = rna_tf32(v.z); v.w = rna_tf32(v.w);
    dst[j] = v;
}

// ===========================================================================
// tf32 mma.sync GEMM: C[M,N] = A[M,K] * Bw[N,K]^T + bias[N]
// R9/R10 champion: CTA 128x128, 8 warps, warp 64x32, BK=32, 3-stage,
// 2 CTAs/SM, cp.async interleaved into the 4 k-steps.  (UNCHANGED)
// ===========================================================================
#define BKC 32
#define SROW 36
#define STAGE_FLOATS (128 * SROW)
#define STAGE_BYTES  (2 * STAGE_FLOATS * 4)
#define NSTG 3
#define GEMM_SMEM (NSTG * STAGE_BYTES)      // 110592

__global__ __launch_bounds__(256, 2)
void gemm_tf32_mma(const float* __restrict__ A, const float* __restrict__ Bw,
                   const float* __restrict__ bias, float* __restrict__ C, int N)
{
    extern __shared__ float sm[];

    const int tid  = threadIdx.x;
    const int wid  = tid >> 5;
    const int lane = tid & 31;
    const int wm   = wid & 1;
    const int wn   = wid >> 1;
    const int lr   = lane >> 2;
    const int lc   = lane & 3;
    const long m0 = (long)blockIdx.y * 128;
    const long n0 = (long)blockIdx.x * 128;

    const float* Abase = A  + m0 * GK;
    const float* Bbase = Bw + n0 * GK;

    const uint32_t smem0 = smem_u32(sm);
    const uint32_t aoff = ((wm * 64 + (lane & 15)) * SROW + 4 * (lane >> 4)) * 4;
    const uint32_t boff = ((wn * 32 + (lane & 7)) * SROW + 4 * ((lane >> 3) & 1)) * 4
                          + STAGE_FLOATS * 4;

    const int ld_row0 = tid >> 3;
    const int ld_c    = tid & 7;

    float acc[4][4][4];
#pragma unroll
    for (int i = 0; i < 4; ++i)
#pragma unroll
        for (int j = 0; j < 4; ++j)
#pragma unroll
            for (int q = 0; q < 4; ++q) acc[i][j][q] = 0.0f;

#pragma unroll
    for (int p = 0; p < 2; ++p) {
        uint32_t sa = smem0 + p * STAGE_BYTES;
        uint32_t sb = sa + STAGE_FLOATS * 4;
        const float* Ab = Abase + p * BKC;
        const float* Bb = Bbase + p * BKC;
#pragma unroll
        for (int it = 0; it < 4; ++it) {
            int row = ld_row0 + it * 32;
            CP_ASYNC16(sa + row * (SROW * 4) + ld_c * 16, Ab + (long)row * GK + ld_c * 4);
            CP_ASYNC16(sb + row * (SROW * 4) + ld_c * 16, Bb + (long)row * GK + ld_c * 4);
        }
        CP_COMMIT();
    }

    const int KT = GK / BKC;   // 64
    for (int kt = 0; kt < KT; ++kt) {
        CP_WAIT(1);
        __syncthreads();

        const uint32_t stage = smem0 + (kt % NSTG) * STAGE_BYTES;

        const int nf = kt + 2;
        const bool do_load = (nf < KT);
        const uint32_t nsa = smem0 + (nf % NSTG) * STAGE_BYTES;
        const uint32_t nsb = nsa + STAGE_FLOATS * 4;
        const float* An = Abase + (long)nf * BKC;
        const float* Bn = Bbase + (long)nf * BKC;

#pragma unroll
        for (int k = 0; k < 4; ++k) {
            const uint32_t kb = k * 32;
            uint32_t af[4][4], bf[4][2];
#pragma unroll
            for (int mt = 0; mt < 4; ++mt)
                ldsm_x4(af[mt][0], af[mt][1], af[mt][2], af[mt][3],
                        stage + aoff + mt * (16 * SROW * 4) + kb);
#pragma unroll
            for (int nt = 0; nt < 4; ++nt)
                ldsm_x2(bf[nt][0], bf[nt][1],
                        stage + boff + nt * (8 * SROW * 4) + kb);

            if (do_load) {
                int row = ld_row0 + k * 32;
                CP_ASYNC16(nsa + row * (SROW * 4) + ld_c * 16, An + (long)row * GK + ld_c * 4);
                CP_ASYNC16(nsb + row * (SROW * 4) + ld_c * 16, Bn + (long)row * GK + ld_c * 4);
            }

#pragma unroll
            for (int mt = 0; mt < 4; ++mt)
#pragma unroll
                for (int nt = 0; nt < 4; ++nt)
                    mma_tf32(acc[mt][nt][0], acc[mt][nt][1], acc[mt][nt][2], acc[mt][nt][3],
                             af[mt][0], af[mt][1], af[mt][2], af[mt][3],
                             bf[nt][0], bf[nt][1],
                             acc[mt][nt][0], acc[mt][nt][1], acc[mt][nt][2], acc[mt][nt][3]);
        }
        CP_COMMIT();
    }

#pragma unroll
    for (int mt = 0; mt < 4; ++mt) {
        const long r0 = m0 + wm * 64 + mt * 16 + lr;
#pragma unroll
        for (int nt = 0; nt < 4; ++nt) {
            const long cc = n0 + wn * 32 + nt * 8 + 2 * lc;
            const float b0 = bias[cc], b1 = bias[cc + 1];
            float2 v0 = make_float2(acc[mt][nt][0] + b0, acc[mt][nt][1] + b1);
            float2 v1 = make_float2(acc[mt][nt][2] + b0, acc[mt][nt][3] + b1);
            *(float2*)(C + r0 * N + cc)       = v0;
            *(float2*)(C + (r0 + 8) * N + cc) = v1;
        }
    }
}

// ===========================================================================
// Tensor-core flash attention (causal), tf32 mma.sync.
// R12: R10 base (register-prefetch pipeline, in-kernel split) with all
// Q/K/P fragment loads converted to ldmatrix (4x fewer LSU issues in QK).
// Loaded values bit-identical -> rel_err unchanged.
// ===========================================================================
#define ATT_QHI 0
#define ATT_QLO 16896
#define ATT_KHI 33792
#define ATT_KLO 38016
#define ATT_VS  42240
#define ATT_PS  46592
#define ATT_SMEM_FLOATS 51200
#define ATT_SMEM_BYTES (ATT_SMEM_FLOATS * 4)   // 204800

__global__ __launch_bounds__(256, 1)
void flash_attn_tc(const float* __restrict__ qkv, float* __restrict__ out)
{
    extern __shared__ float sm[];
    float* Qhi = sm + ATT_QHI;
    float* Qlo = sm + ATT_QLO;
    float* Khi = sm + ATT_KHI;
    float* Klo = sm + ATT_KLO;
    float* Vsm = sm + ATT_VS;
    float* Psm = sm + ATT_PS;

    const int tid  = threadIdx.x;
    const int wid  = tid >> 5;
    const int lane = tid & 31;
    const int lr   = lane >> 2;
    const int lc   = lane & 3;
    const int qi   = (int)(gridDim.x - 1) - (int)blockIdx.x;
    const int h    = blockIdx.y;
    const int b    = blockIdx.z;
    const int q0   = qi * 128;
    const int m0   = wid * 16;

    const float SCL2E = 0.08838834764831845f * 1.4426950408889634f;

    const float* baseQ = qkv + ((long)b * SEQ) * THREE_E + h * HDIM;
    const float* baseK = baseQ + EMB;
    const float* baseV = baseQ + 2 * EMB;

    const uint32_t smem0 = smem_u32(sm);
    // ldmatrix base addresses (bytes), proven GEMM formulas with stride 132
    const uint32_t qhi_a = smem0 + ATT_QHI * 4
        + ((m0 + (lane & 15)) * 132 + 4 * (lane >> 4)) * 4;
    const uint32_t qlo_a = qhi_a + (ATT_QLO - ATT_QHI) * 4;
    const uint32_t khi_b = smem0 + ATT_KHI * 4
        + ((((lane >> 4) & 1) * 8 + (lane & 7)) * 132 + 4 * ((lane >> 3) & 1)) * 4;
    const uint32_t klo_b = khi_b + (ATT_KLO - ATT_KHI) * 4;
    const uint32_t p_a   = smem0 + ATT_PS * 4
        + ((m0 + (lane & 15)) * 36 + 4 * (lane >> 4)) * 4;

    // This thread's 4 slots within a 32x128 tile: row = slot>>5, d = (slot&31)*4
    const int srow[4] = { tid >> 5, (tid + 256) >> 5, (tid + 512) >> 5, (tid + 768) >> 5 };
    const int sd     = (tid & 31) * 4;

    // ---- Prefetch tile 0 into registers ----
    float4 kreg[4], vreg[4];
#pragma unroll
    for (int i = 0; i < 4; ++i) {
        const long gr = (long)srow[i] * THREE_E + sd;
        kreg[i] = *(const float4*)(baseK + gr);
        vreg[i] = *(const float4*)(baseV + gr);
    }

    // ---- Load Q tile with hi/lo tf32 split ----
#pragma unroll
    for (int i = 0; i < 16; ++i) {
        int slot = tid + i * 256;
        int row  = slot >> 5;
        int d    = (slot & 31) * 4;
        float4 v = *(const float4*)(baseQ + (long)(q0 + row) * THREE_E + d);
        float4 hi, lo;
        hi.x = rna_tf32(v.x); lo.x = rna_tf32(v.x - hi.x);
        hi.y = rna_tf32(v.y); lo.y = rna_tf32(v.y - hi.y);
        hi.z = rna_tf32(v.z); lo.z = rna_tf32(v.z - hi.z);
        hi.w = rna_tf32(v.w); lo.w = rna_tf32(v.w - hi.w);
        *(float4*)(Qhi + row * 132 + d) = hi;
        *(float4*)(Qlo + row * 132 + d) = lo;
    }

    float oacc[16][4];
#pragma unroll
    for (int nt = 0; nt < 16; ++nt)
#pragma unroll
        for (int q = 0; q < 4; ++q) oacc[nt][q] = 0.0f;
    float m_lo = -1e30f, m_hi = -1e30f;
    float l_lo = 0.0f,   l_hi = 0.0f;

    const int row_lo = q0 + m0 + lr;
    const int row_hi = row_lo + 8;

    const int ktEnd = 4 * qi + 3;
    for (int kt = 0; kt <= ktEnd; ++kt) {
        __syncthreads();   // previous iteration done reading K/V/P smem

        // ---- Store prefetched tile kt to smem (hi/lo split K, RNA V) ----
#pragma unroll
        for (int i = 0; i < 4; ++i) {
            const int row = srow[i];
            float4 kv = kreg[i];
            float4 hi, lo;
            hi.x = rna_tf32(kv.x); lo.x = rna_tf32(kv.x - hi.x);
            hi.y = rna_tf32(kv.y); lo.y = rna_tf32(kv.y - hi.y);
            hi.z = rna_tf32(kv.z); lo.z = rna_tf32(kv.z - hi.z);
            hi.w = rna_tf32(kv.w); lo.w = rna_tf32(kv.w - hi.w);
            *(float4*)(Khi + row * 132 + sd) = hi;
            *(float4*)(Klo + row * 132 + sd) = lo;
            float4 vv = vreg[i];
            vv.x = rna_tf32(vv.x); vv.y = rna_tf32(vv.y);
            vv.z = rna_tf32(vv.z); vv.w = rna_tf32(vv.w);
            *(float4*)(Vsm + row * 136 + sd) = vv;
        }
        __syncthreads();

        // ---- Prefetch tile kt+1 into registers (overlaps with compute) ----
        if (kt < ktEnd) {
            const long tb = (long)((kt + 1) * 32);
#pragma unroll
            for (int i = 0; i < 4; ++i) {
                const long gr = (tb + srow[i]) * THREE_E + sd;
                kreg[i] = *(const float4*)(baseK + gr);
                vreg[i] = *(const float4*)(baseV + gr);
            }
        }

        if (kt * 32 > q0 + m0 + 15) continue;   // warp-tile fully masked

        // ---- S = Q K^T via 3xTF32, ldmatrix fragments ----
        float sacc[4][4];
#pragma unroll
        for (int nt = 0; nt < 4; ++nt)
#pragma unroll
            for (int q = 0; q < 4; ++q) sacc[nt][q] = 0.0f;

#pragma unroll
        for (int kd = 0; kd < 16; ++kd) {
            const uint32_t kb = kd * 32;
            uint32_t ah[4], al[4], bh[4][2], bl[4][2];
            ldsm_x4(ah[0], ah[1], ah[2], ah[3], qhi_a + kb);
            ldsm_x4(al[0], al[1], al[2], al[3], qlo_a + kb);
            ldsm_x4(bh[0][0], bh[0][1], bh[1][0], bh[1][1], khi_b + kb);
            ldsm_x4(bh[2][0], bh[2][1], bh[3][0], bh[3][1], khi_b + 16 * 132 * 4 + kb);
            ldsm_x4(bl[0][0], bl[0][1], bl[1][0], bl[1][1], klo_b + kb);
            ldsm_x4(bl[2][0], bl[2][1], bl[3][0], bl[3][1], klo_b + 16 * 132 * 4 + kb);
#pragma unroll
            for (int nt = 0; nt < 4; ++nt) {
                mma_tf32(sacc[nt][0], sacc[nt][1], sacc[nt][2], sacc[nt][3],
                         ah[0], ah[1], ah[2], ah[3], bh[nt][0], bh[nt][1],
                         sacc[nt][0], sacc[nt][1], sacc[nt][2], sacc[nt][3]);
                mma_tf32(sacc[nt][0], sacc[nt][1], sacc[nt][2], sacc[nt][3],
                         ah[0], ah[1], ah[2], ah[3], bl[nt][0], bl[nt][1],
                         sacc[nt][0], sacc[nt][1], sacc[nt][2], sacc[nt][3]);
                mma_tf32(sacc[nt][0], sacc[nt][1], sacc[nt][2], sacc[nt][3],
                         al[0], al[1], al[2], al[3], bh[nt][0], bh[nt][1],
                         sacc[nt][0], sacc[nt][1], sacc[nt][2], sacc[nt][3]);
            }
        }

        // ---- Online softmax (base-2) ----
        const bool tail = (kt >= 4 * qi);
        float rm_lo = -INFINITY, rm_hi = -INFINITY;
#pragma unroll
        for (int nt = 0; nt < 4; ++nt) {
            const int c0 = kt * 32 + nt * 8 + 2 * lc;
            float v0 = sacc[nt][0] * SCL2E;
            float v1 = sacc[nt][1] * SCL2E;
            float v2 = sacc[nt][2] * SCL2E;
            float v3 = sacc[nt][3] * SCL2E;
            if (tail) {
                if (c0     > row_lo) v0 = -INFINITY;
                if (c0 + 1 > row_lo) v1 = -INFINITY;
                if (c0     > row_hi) v2 = -INFINITY;
                if (c0 + 1 > row_hi) v3 = -INFINITY;
            }
            sacc[nt][0] = v0; sacc[nt][1] = v1;
            sacc[nt][2] = v2; sacc[nt][3] = v3;
            rm_lo = fmaxf(rm_lo, fmaxf(v0, v1));
            rm_hi = fmaxf(rm_hi, fmaxf(v2, v3));
        }
        rm_lo = fmaxf(rm_lo, __shfl_xor_sync(0xffffffffu, rm_lo, 1));
        rm_lo = fmaxf(rm_lo, __shfl_xor_sync(0xffffffffu, rm_lo, 2));
        rm_hi = fmaxf(rm_hi, __shfl_xor_sync(0xffffffffu, rm_hi, 1));
        rm_hi = fmaxf(rm_hi, __shfl_xor_sync(0xffffffffu, rm_hi, 2));

        const float mn_lo = fmaxf(m_lo, rm_lo);
        const float mn_hi = fmaxf(m_hi, rm_hi);
        const float corr_lo = ex2(m_lo - mn_lo);
        const float corr_hi = ex2(m_hi - mn_hi);
        m_lo = mn_lo; m_hi = mn_hi;

        float ps_lo = 0.0f, ps_hi = 0.0f;
#pragma unroll
        for (int nt = 0; nt < 4; ++nt) {
            float p0 = ex2(sacc[nt][0] - mn_lo);
            float p1 = ex2(sacc[nt][1] - mn_lo);
            float p2 = ex2(sacc[nt][2] - mn_hi);
            float p3 = ex2(sacc[nt][3] - mn_hi);
            ps_lo += p0 + p1;
            ps_hi += p2 + p3;
            float2 w0 = make_float2(rna_tf32(p0), rna_tf32(p1));
            float2 w1 = make_float2(rna_tf32(p2), rna_tf32(p3));
            *(float2*)(Psm + (m0 + lr    ) * 36 + nt * 8 + 2 * lc) = w0;
            *(float2*)(Psm + (m0 + lr + 8) * 36 + nt * 8 + 2 * lc) = w1;
        }
        ps_lo += __shfl_xor_sync(0xffffffffu, ps_lo, 1);
        ps_lo += __shfl_xor_sync(0xffffffffu, ps_lo, 2);
        ps_hi += __shfl_xor_sync(0xffffffffu, ps_hi, 1);
        ps_hi += __shfl_xor_sync(0xffffffffu, ps_hi, 2);
        l_lo = l_lo * corr_lo + ps_lo;
        l_hi = l_hi * corr_hi + ps_hi;

#pragma unroll
        for (int nt = 0; nt < 16; ++nt) {
            oacc[nt][0] *= corr_lo; oacc[nt][1] *= corr_lo;
            oacc[nt][2] *= corr_hi; oacc[nt][3] *= corr_hi;
        }
        __syncwarp();

        // ---- O += P V  (P via ldmatrix, V scalar conflict-free) ----
        const uint32_t* vs = (const uint32_t*)Vsm;
#pragma unroll
        for (int kd = 0; kd < 4; ++kd) {
            const int k0 = kd * 8;
            uint32_t a0, a1, a2, a3;
            ldsm_x4(a0, a1, a2, a3, p_a + kd * 32);
#pragma unroll
            for (int nt = 0; nt < 16; ++nt) {
                uint32_t b0 = vs[(k0 + lc    ) * 136 + nt * 8 + lr];
                uint32_t b1 = vs[(k0 + lc + 4) * 136 + nt * 8 + lr];
                mma_tf32(oacc[nt][0], oacc[nt][1], oacc[nt][2], oacc[nt][3],
                         a0, a1, a2, a3, b0, b1,
                         oacc[nt][0], oacc[nt][1], oacc[nt][2], oacc[nt][3]);
            }
        }
    }

    const float inv_lo = 1.0f / l_lo;
    const float inv_hi = 1.0f / l_hi;
    const long grow_lo = (long)b * SEQ + row_lo;
    const long grow_hi = (long)b * SEQ + row_hi;
#pragma unroll
    for (int nt = 0; nt < 16; ++nt) {
        const int col = h * HDIM + nt * 8 + 2 * lc;
        float2 w0 = make_float2(rna_tf32(oacc[nt][0] * inv_lo),
                                rna_tf32(oacc[nt][1] * inv_lo));
        float2 w1 = make_float2(rna_tf32(oacc[nt][2] * inv_hi),
                                rna_tf32(oacc[nt][3] * inv_hi));
        *(float2*)(out + grow_lo * EMB + col) = w0;
        *(float2*)(out + grow_hi * EMB + col) = w1;
    }
}

// ===========================================================================
// Host launcher
// ===========================================================================
extern "C" void kernel_launch(void* const* d_in, const int* in_sizes, int n_in,
                              void* d_out, int out_size)
{
    const float* x     = (const float*)d_in[0];
    const float* Wqkv  = (const float*)d_in[1];
    const float* bqkv  = (const float*)d_in[2];
    const float* Wout  = (const float*)d_in[3];
    const float* bout  = (const float*)d_in[4];
    float* out = (float*)d_out;

    float *qkvp, *attnp, *xr, *wqkvr, *woutr;
    cudaGetSymbolAddress((void**)&qkvp,  g_qkv);
    cudaGetSymbolAddress((void**)&attnp, g_attn);
    cudaGetSymbolAddress((void**)&xr,    g_xr);
    cudaGetSymbolAddress((void**)&wqkvr, g_wqkvr);
    cudaGetSymbolAddress((void**)&woutr, g_woutr);

    // 0) tf32 pre-rounding of all GEMM operands (single fused launch)
    {
        int n4 = N4X + N4Q + N4O;
        round_all_kernel<<<(n4 + 255) / 256, 256>>>(x, xr, Wqkv, wqkvr, Wout, woutr);
    }

    cudaFuncSetAttribute(gemm_tf32_mma, cudaFuncAttributeMaxDynamicSharedMemorySize, GEMM_SMEM);

    // 1) QKV projection
    {
        dim3 grid(THREE_E / 128, MROWS / 128);   // 48 x 32
        gemm_tf32_mma<<<grid, 256, GEMM_SMEM>>>(xr, wqkvr, bqkv, qkvp, THREE_E);
    }

    // 2) Tensor-core flash attention (ldmatrix fragments)
    {
        cudaFuncSetAttribute(flash_attn_tc, cudaFuncAttributeMaxDynamicSharedMemorySize, ATT_SMEM_BYTES);
        dim3 grid(SEQ / 128, NHEAD, BATCH);
        flash_attn_tc<<<grid, 256, ATT_SMEM_BYTES>>>(qkvp, attnp);
    }

    // 3) Output projection
    {
        dim3 grid(EMB / 128, MROWS / 128);       // 16 x 32
        gemm_tf32_mma<<<grid, 256, GEMM_SMEM>>>(attnp, woutr, bout, out, EMB);
    }
}